// round 7
// baseline (speedup 1.0000x reference)
#include <cuda_runtime.h>

#define NB   8192
#define NOPT 16
#define DIM  768
#define F4_PER_ROW (DIM / 4)   // 192 float4 per row
#define MARGIN 0.3f
#define GRID (NB / 2)

// Scratch: per-sample partials + completion counter (deterministic reduction).
__device__ float    g_loss[NB];
__device__ int      g_cnt[NB];
__device__ unsigned cf_counter = 0;   // returns to 0 at end of every launch

// Pair ownership: warp0 = intra-A (i,j<8) + cross rows i<4; warp1 = rest.
__device__ __host__ constexpr bool owns(int w, int i, int j) {
    if (j < 8)  return w == 0;               // intra-A
    if (i >= 8) return w == 1;               // intra-B
    return (i < 4) ? (w == 0) : (w == 1);    // cross split by i
}

// Compile-time index of pair (i,j) within warp W's 68-entry accumulator.
template <int W>
__device__ __host__ constexpr int local_idx(int i, int j) {
    int c = 0;
    for (int a = 0; a < NOPT; ++a)
        for (int b = a; b < NOPT; ++b) {
            if (a == i && b == j) return c;
            if (owns(W, a, b)) ++c;
        }
    return 0;
}

__device__ __forceinline__ void fma4(float& a, const float4& u, const float4& v) {
    a = fmaf(u.x, v.x, a);
    a = fmaf(u.y, v.y, a);
    a = fmaf(u.z, v.z, a);
    a = fmaf(u.w, v.w, a);
}

template <int W>
__device__ __forceinline__ void sample_work(const float4* __restrict__ base,
                                            float* __restrict__ G, int lane) {
    float acc[68] = {};
    constexpr int R0 = (W == 0) ? 0 : 8;     // own 8-row block

    for (int k = 0; k < 6; ++k) {
        const float4* p0 = base + lane + 32 * k;
        float4 x[8];
#pragma unroll
        for (int n = 0; n < 8; ++n) x[n] = p0[(R0 + n) * F4_PER_ROW];

        // Intra-block pairs (36)
#pragma unroll
        for (int i = 0; i < 8; ++i)
#pragma unroll
            for (int j = i; j < 8; ++j)
                fma4(acc[local_idx<W>(R0 + i, R0 + j)], x[i], x[j]);

        // Cross pairs (32): stream the other block one row at a time
        if (W == 0) {
#pragma unroll
            for (int j = 8; j < 16; ++j) {
                const float4 b = p0[j * F4_PER_ROW];
#pragma unroll
                for (int i = 0; i < 4; ++i)
                    fma4(acc[local_idx<0>(i, j)], x[i], b);
            }
        } else {
#pragma unroll
            for (int i = 4; i < 8; ++i) {
                const float4 a = p0[i * F4_PER_ROW];
#pragma unroll
                for (int j = 8; j < 16; ++j)
                    fma4(acc[local_idx<1>(i, j)], a, x[j - 8]);
            }
        }
    }

    // Cross-lane reduce + store to G (same shfl tree as the passing kernels).
#pragma unroll
    for (int i = 0; i < NOPT; ++i)
#pragma unroll
        for (int j = i; j < NOPT; ++j)
            if (owns(W, i, j)) {
                float v = acc[local_idx<W>(i, j)];
                v += __shfl_xor_sync(0xFFFFFFFFu, v, 16);
                v += __shfl_xor_sync(0xFFFFFFFFu, v, 8);
                v += __shfl_xor_sync(0xFFFFFFFFu, v, 4);
                v += __shfl_xor_sync(0xFFFFFFFFu, v, 2);
                v += __shfl_xor_sync(0xFFFFFFFFu, v, 1);
                if (lane == 0) {
                    G[i * NOPT + j] = v;
                    G[j * NOPT + i] = v;
                }
            }
}

// 128 threads = 2 samples x 2 warps; 4 CTAs/SM (reg-capped) = 16 warps/SM.
__global__ void __launch_bounds__(128, 4)
cf_fused(const float* __restrict__ emb, const long long* __restrict__ labels,
         float* __restrict__ out) {
    __shared__ float G[2][NOPT * NOPT];
    __shared__ float invn[2][NOPT];
    __shared__ int   lab[2][NOPT];
    __shared__ float ssum[4];
    __shared__ int   scnt[4];
    __shared__ int   s_last;

    const int tid  = threadIdx.x;
    const int half = tid >> 6;            // sample within CTA
    const int ht   = tid & 63;            // thread within sample group
    const int wis  = (tid >> 5) & 1;      // warp-in-sample 0..1
    const int lane = tid & 31;
    const int b    = blockIdx.x * 2 + half;

    if (ht < NOPT) lab[half][ht] = (int)labels[(size_t)b * NOPT + ht];

    const float4* base = reinterpret_cast<const float4*>(emb + (size_t)b * NOPT * DIM);

    if (wis == 0) sample_work<0>(base, G[half], lane);
    else          sample_work<1>(base, G[half], lane);
    __syncthreads();

    if (ht < NOPT) invn[half][ht] = rsqrtf(fmaxf(G[half][ht * NOPT + ht], 1e-24f));
    __syncthreads();

    if (ht < NOPT) {
        const int  n     = ht;
        const bool isPos = (lab[half][n] == 1);
        const bool isNeg = (lab[half][n] == 0);
        const unsigned posm = __ballot_sync(0x0000FFFFu, isPos) & 0xFFFFu;
        const unsigned negm = __ballot_sync(0x0000FFFFu, isNeg) & 0xFFFFu;
        const bool valid = (posm != 0u) && (negm != 0u);

        const float in_ = invn[half][n];
        float mx = -1e9f;   // NEG_INF sentinel, matches reference
#pragma unroll
        for (int m = 0; m < NOPT; ++m) {
            if (lab[half][m] == 0)
                mx = fmaxf(mx, G[half][n * NOPT + m] * in_ * invn[half][m]);
        }
        const float trip = fmaxf(mx + MARGIN, 0.0f);
        float contrib = (isPos && valid) ? trip : 0.0f;

        contrib += __shfl_xor_sync(0x0000FFFFu, contrib, 8);
        contrib += __shfl_xor_sync(0x0000FFFFu, contrib, 4);
        contrib += __shfl_xor_sync(0x0000FFFFu, contrib, 2);
        contrib += __shfl_xor_sync(0x0000FFFFu, contrib, 1);

        if (n == 0) {
            g_loss[b] = contrib;
            g_cnt[b]  = valid ? __popc(posm) : 0;
        }
    }

    // Publish then arrive; last CTA reduces (deterministic fixed order).
    if (ht == 0) __threadfence();
    __syncthreads();
    if (tid == 0) {
        const unsigned t = atomicAdd(&cf_counter, 1u);
        s_last = (t == GRID - 1);
    }
    __syncthreads();

    if (s_last) {
        __threadfence();   // order counter observation before partial reads
        float s = 0.0f;
        int   c = 0;
#pragma unroll 8
        for (int i = tid; i < NB; i += 128) {
            s += __ldcg(&g_loss[i]);
            c += __ldcg(&g_cnt[i]);
        }
#pragma unroll
        for (int off = 16; off > 0; off >>= 1) {
            s += __shfl_xor_sync(0xFFFFFFFFu, s, off);
            c += __shfl_xor_sync(0xFFFFFFFFu, c, off);
        }
        if (lane == 0) { ssum[tid >> 5] = s; scnt[tid >> 5] = c; }
        __syncthreads();
        if (tid == 0) {
            const float st = (ssum[0] + ssum[1]) + (ssum[2] + ssum[3]);
            const int   ct = (scnt[0] + scnt[1]) + (scnt[2] + scnt[3]);
            out[0] = st / (float)(ct > 0 ? ct : 1);
            cf_counter = 0;   // reset for next graph replay
        }
    }
}

extern "C" void kernel_launch(void* const* d_in, const int* in_sizes, int n_in,
                              void* d_out, int out_size) {
    const float*     emb    = (const float*)d_in[0];
    const long long* labels = (const long long*)d_in[1];
    float*           out    = (float*)d_out;

    cf_fused<<<GRID, 128>>>(emb, labels, out);
}

// round 9
// speedup vs baseline: 80.7346x; 80.7346x over previous
#include <cuda_runtime.h>

#define NB   8192
#define NOPT 16
#define DIM  768
#define F4_PER_ROW (DIM / 4)   // 192 float4 per row
#define MARGIN 0.3f
#define GRID (NB / 2)

// Scratch: per-sample partials + completion counter (deterministic reduction).
__device__ float    g_loss[NB];
__device__ int      g_cnt[NB];
__device__ unsigned cf_counter = 0;   // returns to 0 at end of every launch

// Triangular index within an 8-row block: i<=j, both 0..7. Closed form ->
// guaranteed constant folding under full unroll (same family as R1's pidx).
__device__ __forceinline__ constexpr int tri8(int i, int j) {
    return i * 8 - (i * (i - 1)) / 2 + (j - i);
}

__device__ __forceinline__ void fma4(float& a, const float4& u, const float4& v) {
    a = fmaf(u.x, v.x, a);
    a = fmaf(u.y, v.y, a);
    a = fmaf(u.z, v.z, a);
    a = fmaf(u.w, v.w, a);
}

__device__ __forceinline__ void shfl_reduce_store(float v, float* G, int i, int j, int lane) {
    v += __shfl_xor_sync(0xFFFFFFFFu, v, 16);
    v += __shfl_xor_sync(0xFFFFFFFFu, v, 8);
    v += __shfl_xor_sync(0xFFFFFFFFu, v, 4);
    v += __shfl_xor_sync(0xFFFFFFFFu, v, 2);
    v += __shfl_xor_sync(0xFFFFFFFFu, v, 1);
    if (lane == 0) {
        G[i * NOPT + j] = v;
        G[j * NOPT + i] = v;
    }
}

// Warp W keeps its own 8-row block resident (x[8] = 32 regs) and owns:
//   W=0: intra-A triangle (36) + cross i in 0..3 x j in 8..15 (32)
//   W=1: intra-B triangle (36) + cross i in 4..7 x j in 8..15 (32)
// acc split into accT[36] (tri8 index) + accC[32] (affine i*8+jj index).
template <int W>
__device__ __forceinline__ void sample_work(const float4* __restrict__ base,
                                            float* __restrict__ G, int lane) {
    constexpr int R0 = W * 8;   // resident block: rows R0..R0+7

    float accT[36] = {};
    float accC[32] = {};

    for (int k = 0; k < 6; ++k) {
        const float4* p0 = base + lane + 32 * k;
        float4 x[8];
#pragma unroll
        for (int n = 0; n < 8; ++n) x[n] = p0[(R0 + n) * F4_PER_ROW];

        // Intra-block triangle (36 pairs)
#pragma unroll
        for (int i = 0; i < 8; ++i)
#pragma unroll
            for (int j = i; j < 8; ++j)
                fma4(accT[tri8(i, j)], x[i], x[j]);

        // Cross pairs (32): stream the non-resident rows one at a time
        if (W == 0) {
#pragma unroll
            for (int jj = 0; jj < 8; ++jj) {
                const float4 bR = p0[(8 + jj) * F4_PER_ROW];
#pragma unroll
                for (int i = 0; i < 4; ++i)
                    fma4(accC[i * 8 + jj], x[i], bR);
            }
        } else {
#pragma unroll
            for (int ii = 0; ii < 4; ++ii) {
                const float4 aR = p0[(4 + ii) * F4_PER_ROW];
#pragma unroll
                for (int jj = 0; jj < 8; ++jj)
                    fma4(accC[ii * 8 + jj], aR, x[jj]);
            }
        }
    }

    // Cross-lane reduce + store to G (same shfl tree as all passing rounds).
#pragma unroll
    for (int i = 0; i < 8; ++i)
#pragma unroll
        for (int j = i; j < 8; ++j)
            shfl_reduce_store(accT[tri8(i, j)], G, R0 + i, R0 + j, lane);

    if (W == 0) {
#pragma unroll
        for (int i = 0; i < 4; ++i)
#pragma unroll
            for (int jj = 0; jj < 8; ++jj)
                shfl_reduce_store(accC[i * 8 + jj], G, i, 8 + jj, lane);
    } else {
#pragma unroll
        for (int ii = 0; ii < 4; ++ii)
#pragma unroll
            for (int jj = 0; jj < 8; ++jj)
                shfl_reduce_store(accC[ii * 8 + jj], G, 4 + ii, 8 + jj, lane);
    }
}

// 128 threads = 2 samples x 2 warps; target 4 CTAs/SM = 16 warps/SM.
__global__ void __launch_bounds__(128, 4)
cf_fused(const float* __restrict__ emb, const long long* __restrict__ labels,
         float* __restrict__ out) {
    __shared__ float G[2][NOPT * NOPT];
    __shared__ float invn[2][NOPT];
    __shared__ int   lab[2][NOPT];
    __shared__ float ssum[4];
    __shared__ int   scnt[4];
    __shared__ int   s_last;

    const int tid  = threadIdx.x;
    const int half = tid >> 6;            // sample within CTA
    const int ht   = tid & 63;            // thread within sample group
    const int wis  = (tid >> 5) & 1;      // warp-in-sample 0..1
    const int lane = tid & 31;
    const int b    = blockIdx.x * 2 + half;

    if (ht < NOPT) lab[half][ht] = (int)labels[(size_t)b * NOPT + ht];

    const float4* base = reinterpret_cast<const float4*>(emb + (size_t)b * NOPT * DIM);

    if (wis == 0) sample_work<0>(base, G[half], lane);
    else          sample_work<1>(base, G[half], lane);
    __syncthreads();

    if (ht < NOPT) invn[half][ht] = rsqrtf(fmaxf(G[half][ht * NOPT + ht], 1e-24f));
    __syncthreads();

    if (ht < NOPT) {
        const int  n     = ht;
        const bool isPos = (lab[half][n] == 1);
        const bool isNeg = (lab[half][n] == 0);
        const unsigned posm = __ballot_sync(0x0000FFFFu, isPos) & 0xFFFFu;
        const unsigned negm = __ballot_sync(0x0000FFFFu, isNeg) & 0xFFFFu;
        const bool valid = (posm != 0u) && (negm != 0u);

        const float in_ = invn[half][n];
        float mx = -1e9f;   // NEG_INF sentinel, matches reference
#pragma unroll
        for (int m = 0; m < NOPT; ++m) {
            if (lab[half][m] == 0)
                mx = fmaxf(mx, G[half][n * NOPT + m] * in_ * invn[half][m]);
        }
        const float trip = fmaxf(mx + MARGIN, 0.0f);
        float contrib = (isPos && valid) ? trip : 0.0f;

        contrib += __shfl_xor_sync(0x0000FFFFu, contrib, 8);
        contrib += __shfl_xor_sync(0x0000FFFFu, contrib, 4);
        contrib += __shfl_xor_sync(0x0000FFFFu, contrib, 2);
        contrib += __shfl_xor_sync(0x0000FFFFu, contrib, 1);

        if (n == 0) {
            g_loss[b] = contrib;
            g_cnt[b]  = valid ? __popc(posm) : 0;
        }
    }

    // Publish then arrive; last CTA reduces (deterministic fixed order).
    if (ht == 0) __threadfence();
    __syncthreads();
    if (tid == 0) {
        const unsigned t = atomicAdd(&cf_counter, 1u);
        s_last = (t == GRID - 1);
    }
    __syncthreads();

    if (s_last) {
        __threadfence();   // order counter observation before partial reads
        float s = 0.0f;
        int   c = 0;
#pragma unroll 8
        for (int i = tid; i < NB; i += 128) {
            s += __ldcg(&g_loss[i]);
            c += __ldcg(&g_cnt[i]);
        }
#pragma unroll
        for (int off = 16; off > 0; off >>= 1) {
            s += __shfl_xor_sync(0xFFFFFFFFu, s, off);
            c += __shfl_xor_sync(0xFFFFFFFFu, c, off);
        }
        if (lane == 0) { ssum[tid >> 5] = s; scnt[tid >> 5] = c; }
        __syncthreads();
        if (tid == 0) {
            const float st = (ssum[0] + ssum[1]) + (ssum[2] + ssum[3]);
            const int   ct = (scnt[0] + scnt[1]) + (scnt[2] + scnt[3]);
            out[0] = st / (float)(ct > 0 ? ct : 1);
            cf_counter = 0;   // reset for next graph replay
        }
    }
}

extern "C" void kernel_launch(void* const* d_in, const int* in_sizes, int n_in,
                              void* d_out, int out_size) {
    const float*     emb    = (const float*)d_in[0];
    const long long* labels = (const long long*)d_in[1];
    float*           out    = (float*)d_out;

    cf_fused<<<GRID, 128>>>(emb, labels, out);
}